// round 11
// baseline (speedup 1.0000x reference)
#include <cuda_runtime.h>
#include <cuda_bf16.h>
#include <cstdint>

#define NN 40000
#define HID 128
#define NF 128
#define NG 50
#define TE 128
#define TN 128

typedef unsigned long long ull;

// device scratch (no allocations allowed)
__device__ float g_h[NN * NF];
__device__ float g_agg[NN * NF];

// ===========================================================================
// common helpers
// ===========================================================================
__device__ __forceinline__ void red2(float* p, float a, float b) {
    asm volatile("red.global.add.v2.f32 [%0], {%1,%2};"
                 :: "l"(p), "f"(a), "f"(b) : "memory");
}
__device__ __forceinline__ float ex2f(float x) {
    float r; asm("ex2.approx.f32 %0, %1;" : "=f"(r) : "f"(x)); return r;
}
__device__ __forceinline__ float lg2f(float x) {
    float r; asm("lg2.approx.f32 %0, %1;" : "=f"(r) : "f"(x)); return r;
}
__device__ __forceinline__ float fcosf(float x) {
    float r; asm("cos.approx.f32 %0, %1;" : "=f"(r) : "f"(x)); return r;
}
__device__ __forceinline__ float sspf(float x) {
    float t = ex2f(-fabsf(x) * 1.4426950408889634f);
    return fmaxf(x, 0.0f) + 0.69314718055994531f * (lg2f(1.0f + t) - 1.0f);
}

// ===========================================================================
// mma.sync helpers (portable; valid on base sm_103 target)
// ===========================================================================
__device__ __forceinline__ uint32_t smem_u32(const void* p) {
    uint32_t a;
    asm("{ .reg .u64 t; cvta.to.shared.u64 t, %1; cvt.u32.u64 %0, t; }"
        : "=r"(a) : "l"(p));
    return a;
}
__device__ __forceinline__ void ldmx4(unsigned* r, uint32_t addr) {
    asm volatile("ldmatrix.sync.aligned.m8n8.x4.shared.b16 {%0,%1,%2,%3}, [%4];"
        : "=r"(r[0]), "=r"(r[1]), "=r"(r[2]), "=r"(r[3]) : "r"(addr));
}
__device__ __forceinline__ void mma16816(float* c, const unsigned* a,
                                         unsigned b0, unsigned b1) {
    asm volatile(
        "mma.sync.aligned.m16n8k16.row.col.f32.bf16.bf16.f32 "
        "{%0,%1,%2,%3}, {%4,%5,%6,%7}, {%8,%9}, {%0,%1,%2,%3};"
        : "+f"(c[0]), "+f"(c[1]), "+f"(c[2]), "+f"(c[3])
        : "r"(a[0]), "r"(a[1]), "r"(a[2]), "r"(a[3]), "r"(b0), "r"(b1));
}
// byte offset of bf16 element (r, c) in a swizzled tile with row stride rs bytes
__device__ __forceinline__ int phy(int r, int c, int rs) {
    return r * rs + ((((c >> 3) ^ (r & 7))) << 4) + ((c & 7) << 1);
}
__device__ __forceinline__ void split_bf16(float v, __nv_bfloat16& h, __nv_bfloat16& lo) {
    h = __float2bfloat16_rn(v);
    lo = __float2bfloat16_rn(v - __bfloat162float(h));
}

// warp-level m16 x n64 x (16*KSTEPS) bf16-split GEMM, C += A@W^T
template<int KSTEPS, int RSA, int RSW>
__device__ __forceinline__ void warp_mma(uint32_t aH, uint32_t aL,
                                         uint32_t wH, uint32_t wL,
                                         int m0, int fbase, int lane,
                                         float C[8][4]) {
#pragma unroll
    for (int ks = 0; ks < KSTEPS; ks++) {
        unsigned Ah[4], Al[4];
        int ra = m0 + (lane & 7) + ((lane >> 3) & 1) * 8;
        int ca = 2 * ks + (lane >> 4);
        uint32_t aoff = (uint32_t)(ra * RSA + ((ca ^ (ra & 7)) << 4));
        ldmx4(Ah, aH + aoff);
        ldmx4(Al, aL + aoff);
#pragma unroll
        for (int ntp = 0; ntp < 4; ntp++) {
            int rb = fbase + 16 * ntp + (lane & 7) + (lane >> 4) * 8;
            int cb = 2 * ks + ((lane >> 3) & 1);
            uint32_t boff = (uint32_t)(rb * RSW + ((cb ^ (rb & 7)) << 4));
            unsigned Bh[4], Bl[4];
            ldmx4(Bh, wH + boff);
            ldmx4(Bl, wL + boff);
            int j = 2 * ntp;
            mma16816(C[j], Ah, Bh[0], Bh[1]);
            mma16816(C[j], Al, Bh[0], Bh[1]);
            mma16816(C[j], Ah, Bl[0], Bl[1]);
            mma16816(C[j + 1], Ah, Bh[2], Bh[3]);
            mma16816(C[j + 1], Al, Bh[2], Bh[3]);
            mma16816(C[j + 1], Ah, Bl[2], Bl[3]);
        }
    }
}

// ===========================================================================
// edge kernel smem layout (bytes)
// ===========================================================================
#define O_W1H   0
#define O_W1L   16384
#define O_W2H   32768
#define O_W2L   65536
#define O_A1H   98304
#define O_A1L   114688
#define O_TSH   131072
#define O_TSL   163840
#define O_SC    196608
#define O_SSRC  197120
#define O_SDST  197632
#define O_SB1   198144
#define O_SB2   198656
#define EDGE_SMEM 199168

// ---------------------------------------------------------------------------
// per-tile prefetch (registers) and store-to-smem
// ---------------------------------------------------------------------------
__device__ __forceinline__ void pref_tile(const float* __restrict__ ea,
                                          const int* __restrict__ eidx,
                                          const float* __restrict__ ew,
                                          int ebase, int tid, int E,
                                          float pr[13], float& pwv,
                                          int& psv, int& pdv, int& pok) {
#pragma unroll
    for (int i = 0; i < 13; i++) {
        int idx = tid + (i << 9);
        float v = 0.f;
        if (idx < TE * NG) {
            int e = idx / NG;
            if (ebase + e < E) v = ea[ebase * NG + idx];
        }
        pr[i] = v;
    }
    if (tid < TE) {
        int e = ebase + tid;
        pok = (e < E);
        if (pok) { pwv = ew[e]; psv = eidx[e]; pdv = eidx[E + e]; }
        else { pwv = 0.f; psv = 0; pdv = 0; }
    }
}

__device__ __forceinline__ void store_tile(char* smem, int tid,
                                           const float pr[13], float pwv,
                                           int psv, int pdv, int pok,
                                           float* sC, int* ssrc, int* sdst) {
#pragma unroll
    for (int i = 0; i < 13; i++) {
        int idx = tid + (i << 9);
        if (idx < TE * NG) {
            int e = idx / NG, k = idx - e * NG;
            __nv_bfloat16 h, lo; split_bf16(pr[i], h, lo);
            int o = phy(e, k, 128);
            *(__nv_bfloat16*)(smem + O_A1H + o) = h;
            *(__nv_bfloat16*)(smem + O_A1L + o) = lo;
        }
    }
    if (tid < TE) {
        sC[tid] = pok ? 0.5f * (fcosf(pwv * 0.31415926535897932f) + 1.0f) : 0.f;
        ssrc[tid] = psv;
        sdst[tid] = pdv;
    }
}

// ---------------------------------------------------------------------------
// Fused edge kernel on mma.sync tensor cores (bf16 3-product split),
// software-pipelined staging + gather prefetch.
// ---------------------------------------------------------------------------
__global__ __launch_bounds__(512, 1)
void edge_kernel(const float* __restrict__ ea,   // [E][50]
                 const int*   __restrict__ eidx, // [2][E]
                 const float* __restrict__ ew,   // [E]
                 const float* __restrict__ w1,   // [128][50]
                 const float* __restrict__ b1,
                 const float* __restrict__ w2,   // [128][128]
                 const float* __restrict__ b2,
                 int E)
{
    extern __shared__ char smem[];
    uint32_t sbase = smem_u32(smem);
    int tid = threadIdx.x;
    int w = tid >> 5, lane = tid & 31;
    int mw = w & 7;          // edge-row warp (16 rows each)
    int nw = w >> 3;         // filter-col warp (64 cols each)
    int g = lane >> 2, t = lane & 3;

    float* sC   = (float*)(smem + O_SC);
    int*   ssrc = (int*)(smem + O_SSRC);
    int*   sdst = (int*)(smem + O_SDST);
    float* sb1  = (float*)(smem + O_SB1);
    float* sb2  = (float*)(smem + O_SB2);

    // zero W1 + A1 buffers (K padding 50->64 stays zero forever)
    for (int i = tid; i < 4096; i += 512) {
        ((uint32_t*)(smem + O_W1H))[i] = 0; ((uint32_t*)(smem + O_W1L))[i] = 0;
        ((uint32_t*)(smem + O_A1H))[i] = 0; ((uint32_t*)(smem + O_A1L))[i] = 0;
    }
    __syncthreads();

    for (int idx = tid; idx < NF * NG; idx += 512) {
        int f = idx / NG, k = idx - f * NG;
        __nv_bfloat16 h, lo; split_bf16(w1[idx], h, lo);
        int o = phy(f, k, 128);
        *(__nv_bfloat16*)(smem + O_W1H + o) = h;
        *(__nv_bfloat16*)(smem + O_W1L + o) = lo;
    }
    for (int idx = tid; idx < NF * NF; idx += 512) {
        int f = idx >> 7, k = idx & 127;
        __nv_bfloat16 h, lo; split_bf16(w2[idx], h, lo);
        int o = phy(f, k, 256);
        *(__nv_bfloat16*)(smem + O_W2H + o) = h;
        *(__nv_bfloat16*)(smem + O_W2L + o) = lo;
    }
    if (tid < NF) { sb1[tid] = b1[tid]; sb2[tid] = b2[tid]; }

    const uint32_t A1H = sbase + O_A1H, A1L = sbase + O_A1L;
    const uint32_t W1H = sbase + O_W1H, W1L = sbase + O_W1L;
    const uint32_t W2H = sbase + O_W2H, W2L = sbase + O_W2L;
    const uint32_t TSH = sbase + O_TSH, TSL = sbase + O_TSL;

    int e0r = 16 * mw + g;
    int e1r = e0r + 8;
    int ntiles = (E + TE - 1) / TE;

    // prologue prefetch
    float pr[13]; float pwv = 0.f; int psv = 0, pdv = 0, pok = 0;
    int tile = blockIdx.x;
    if (tile < ntiles)
        pref_tile(ea, eidx, ew, tile * TE, tid, E, pr, pwv, psv, pdv, pok);

    for (; tile < ntiles; tile += gridDim.x) {
        int ebase = tile * TE;

        __syncthreads();   // prior tile's readers of A1/Ts/sC done
        store_tile(smem, tid, pr, pwv, psv, pdv, pok, sC, ssrc, sdst);
        __syncthreads();

        // prefetch NEXT tile's edge data (DRAM latency hidden under GEMMs)
        int nt = tile + gridDim.x;
        if (nt < ntiles)
            pref_tile(ea, eidx, ew, nt * TE, tid, E, pr, pwv, psv, pdv, pok);

        // GEMM1 (K=64 padded: 4 k-steps)
        float C[8][4];
#pragma unroll
        for (int j = 0; j < 8; j++)
#pragma unroll
            for (int q = 0; q < 4; q++) C[j][q] = 0.f;
        warp_mma<4, 128, 128>(A1H, A1L, W1H, W1L, 16 * mw, 64 * nw, lane, C);

        // epilogue1: bias + ssp -> split -> Ts
#pragma unroll
        for (int j = 0; j < 8; j++) {
            int f = 64 * nw + 8 * j + 2 * t;
            float bb0 = sb1[f], bb1 = sb1[f + 1];
            float v00 = sspf(C[j][0] + bb0), v01 = sspf(C[j][1] + bb1);
            float v10 = sspf(C[j][2] + bb0), v11 = sspf(C[j][3] + bb1);
            __nv_bfloat16 h0, l0, h1, l1;
            __nv_bfloat162 hh, ll;
            split_bf16(v00, h0, l0); split_bf16(v01, h1, l1);
            hh.x = h0; hh.y = h1; ll.x = l0; ll.y = l1;
            int o0 = phy(e0r, f, 256);
            *(__nv_bfloat162*)(smem + O_TSH + o0) = hh;
            *(__nv_bfloat162*)(smem + O_TSL + o0) = ll;
            split_bf16(v10, h0, l0); split_bf16(v11, h1, l1);
            hh.x = h0; hh.y = h1; ll.x = l0; ll.y = l1;
            int o1 = phy(e1r, f, 256);
            *(__nv_bfloat162*)(smem + O_TSH + o1) = hh;
            *(__nv_bfloat162*)(smem + O_TSL + o1) = ll;
        }
        __syncthreads();

        // prefetch h[src] gathers (L2 latency hidden under GEMM2)
        int ge0 = ebase + e0r, ge1 = ebase + e1r;
        float c0 = sC[e0r], c1 = sC[e1r];
        int s0 = ssrc[e0r], d0 = sdst[e0r];
        int s1 = ssrc[e1r], d1 = sdst[e1r];
        float2 hp0[8], hp1[8];
#pragma unroll
        for (int j = 0; j < 8; j++) {
            int f = 64 * nw + 8 * j + 2 * t;
            hp0[j] = *(const float2*)(g_h + s0 * NF + f);
            hp1[j] = *(const float2*)(g_h + s1 * NF + f);
        }

        // GEMM2 (K=128: 8 k-steps)
#pragma unroll
        for (int j = 0; j < 8; j++)
#pragma unroll
            for (int q = 0; q < 4; q++) C[j][q] = 0.f;
        warp_mma<8, 256, 256>(TSH, TSL, W2H, W2L, 16 * mw, 64 * nw, lane, C);

        // epilogue2: (C + b2) * env * h[src] -> red.v2 agg[dst]
#pragma unroll
        for (int j = 0; j < 8; j++) {
            int f = 64 * nw + 8 * j + 2 * t;
            float bb0 = sb2[f], bb1 = sb2[f + 1];
            if (ge0 < E)
                red2(g_agg + d0 * NF + f,
                     (C[j][0] + bb0) * c0 * hp0[j].x,
                     (C[j][1] + bb1) * c0 * hp0[j].y);
            if (ge1 < E)
                red2(g_agg + d1 * NF + f,
                     (C[j][2] + bb0) * c1 * hp1[j].x,
                     (C[j][3] + bb1) * c1 * hp1[j].y);
        }
    }
}

// ===========================================================================
// lin1 on mma.sync: h = x @ lin1_w^T (no bias); also zeroes g_agg slice.
// smem: WH 0, WL 32768, XH 65536, XL 98304  (131072 bytes)
// ===========================================================================
#define LIN1_SMEM 131072

__global__ __launch_bounds__(512, 1)
void lin1_kernel(const float* __restrict__ x, const float* __restrict__ w, int N) {
    extern __shared__ char smem[];
    uint32_t sbase = smem_u32(smem);
    int tid = threadIdx.x;
    int wp = tid >> 5, lane = tid & 31;
    int mw = wp & 7, nw = wp >> 3;
    int g = lane >> 2, t = lane & 3;

    int nb = blockIdx.x * TN;

    // zero this block's slice of g_agg (replaces zero_agg kernel)
    {
        int zrows = NN - nb; if (zrows > TN) zrows = TN;
        if (zrows > 0) {
            float4* az = (float4*)(g_agg + nb * NF);
            int n4 = zrows * (NF / 4);
            for (int i = tid; i < n4; i += 512)
                az[i] = make_float4(0.f, 0.f, 0.f, 0.f);
        }
    }

    for (int idx = tid; idx < NF * HID; idx += 512) {
        int f = idx >> 7, k = idx & 127;
        __nv_bfloat16 h, lo; split_bf16(w[idx], h, lo);
        int o = phy(f, k, 256);
        *(__nv_bfloat16*)(smem + 0 + o) = h;
        *(__nv_bfloat16*)(smem + 32768 + o) = lo;
    }
    for (int idx = tid; idx < TN * HID; idx += 512) {
        int n = idx >> 7, k = idx & 127;
        float v = (nb + n < N) ? x[(nb + n) * HID + k] : 0.f;
        __nv_bfloat16 h, lo; split_bf16(v, h, lo);
        int o = phy(n, k, 256);
        *(__nv_bfloat16*)(smem + 65536 + o) = h;
        *(__nv_bfloat16*)(smem + 98304 + o) = lo;
    }
    __syncthreads();

    float C[8][4];
#pragma unroll
    for (int j = 0; j < 8; j++)
#pragma unroll
        for (int q = 0; q < 4; q++) C[j][q] = 0.f;
    warp_mma<8, 256, 256>(sbase + 65536, sbase + 98304,
                          sbase + 0, sbase + 32768,
                          16 * mw, 64 * nw, lane, C);

    int r0 = nb + 16 * mw + g, r1 = r0 + 8;
#pragma unroll
    for (int j = 0; j < 8; j++) {
        int f = 64 * nw + 8 * j + 2 * t;
        if (r0 < N) *(float2*)(g_h + r0 * NF + f) = make_float2(C[j][0], C[j][1]);
        if (r1 < N) *(float2*)(g_h + r1 * NF + f) = make_float2(C[j][2], C[j][3]);
    }
}

// ===========================================================================
// out on mma.sync: out = ssp(agg @ lin2^T + b2) @ lin_w^T + bo.
// smem: W2H 0, W2L 32768, WOH 65536, WOL 98304, AH 131072, AL 163840,
//       sb2 196608, sbo 197120   (197632 bytes)
// ===========================================================================
#define OUT_SMEM 197632

__global__ __launch_bounds__(512, 1)
void out_kernel(const float* __restrict__ w2, const float* __restrict__ b2,
                const float* __restrict__ wo, const float* __restrict__ bo,
                float* __restrict__ out, int N)
{
    extern __shared__ char smem[];
    uint32_t sbase = smem_u32(smem);
    int tid = threadIdx.x;
    int wp = tid >> 5, lane = tid & 31;
    int mw = wp & 7, nw = wp >> 3;
    int g = lane >> 2, t = lane & 3;

    float* sb2 = (float*)(smem + 196608);
    float* sbo = (float*)(smem + 197120);

    for (int idx = tid; idx < NF * NF; idx += 512) {
        int f = idx >> 7, k = idx & 127;
        int o = phy(f, k, 256);
        __nv_bfloat16 h, lo;
        split_bf16(w2[idx], h, lo);
        *(__nv_bfloat16*)(smem + 0 + o) = h;
        *(__nv_bfloat16*)(smem + 32768 + o) = lo;
        split_bf16(wo[idx], h, lo);
        *(__nv_bfloat16*)(smem + 65536 + o) = h;
        *(__nv_bfloat16*)(smem + 98304 + o) = lo;
    }
    if (tid < NF) { sb2[tid] = b2[tid]; sbo[tid] = bo[tid]; }

    int nb = blockIdx.x * TN;
    for (int idx = tid; idx < TN * NF; idx += 512) {
        int n = idx >> 7, k = idx & 127;
        float v = (nb + n < N) ? g_agg[(nb + n) * NF + k] : 0.f;
        __nv_bfloat16 h, lo; split_bf16(v, h, lo);
        int o = phy(n, k, 256);
        *(__nv_bfloat16*)(smem + 131072 + o) = h;
        *(__nv_bfloat16*)(smem + 163840 + o) = lo;
    }
    __syncthreads();

    // GEMM1: C = agg @ lin2^T
    float C[8][4];
#pragma unroll
    for (int j = 0; j < 8; j++)
#pragma unroll
        for (int q = 0; q < 4; q++) C[j][q] = 0.f;
    warp_mma<8, 256, 256>(sbase + 131072, sbase + 163840,
                          sbase + 0, sbase + 32768,
                          16 * mw, 64 * nw, lane, C);
    __syncthreads();   // all A reads done before overwrite

    // epilogue: bias + ssp -> split -> back into A buffers (as h2)
    int e0r = 16 * mw + g, e1r = e0r + 8;
#pragma unroll
    for (int j = 0; j < 8; j++) {
        int f = 64 * nw + 8 * j + 2 * t;
        float bb0 = sb2[f], bb1 = sb2[f + 1];
        float v00 = sspf(C[j][0] + bb0), v01 = sspf(C[j][1] + bb1);
        float v10 = sspf(C[j][2] + bb0), v11 = sspf(C[j][3] + bb1);
        __nv_bfloat16 h0, l0, h1, l1;
        __nv_bfloat162 hh, ll;
        split_bf16(v00, h0, l0); split_bf16(v01, h1, l1);
        hh.x = h0; hh.y = h1; ll.x = l0; ll.y = l1;
        int o0 = phy(e0r, f, 256);
        *(__nv_bfloat162*)(smem + 131072 + o0) = hh;
        *(__nv_bfloat162*)(smem + 163840 + o0) = ll;
        split_bf16(v10, h0, l0); split_bf16(v11, h1, l1);
        hh.x = h0; hh.y = h1; ll.x = l0; ll.y = l1;
        int o1 = phy(e1r, f, 256);
        *(__nv_bfloat162*)(smem + 131072 + o1) = hh;
        *(__nv_bfloat162*)(smem + 163840 + o1) = ll;
    }
    __syncthreads();

    // GEMM2: C = h2 @ lin_w^T
#pragma unroll
    for (int j = 0; j < 8; j++)
#pragma unroll
        for (int q = 0; q < 4; q++) C[j][q] = 0.f;
    warp_mma<8, 256, 256>(sbase + 131072, sbase + 163840,
                          sbase + 65536, sbase + 98304,
                          16 * mw, 64 * nw, lane, C);

    int r0 = nb + e0r, r1 = nb + e1r;
#pragma unroll
    for (int j = 0; j < 8; j++) {
        int f = 64 * nw + 8 * j + 2 * t;
        float bb0 = sbo[f], bb1 = sbo[f + 1];
        if (r0 < N)
            *(float2*)(out + r0 * HID + f) = make_float2(C[j][0] + bb0, C[j][1] + bb1);
        if (r1 < N)
            *(float2*)(out + r1 * HID + f) = make_float2(C[j][2] + bb0, C[j][3] + bb1);
    }
}

// ---------------------------------------------------------------------------

extern "C" void kernel_launch(void* const* d_in, const int* in_sizes, int n_in,
                              void* d_out, int out_size) {
    const float* x      = (const float*)d_in[0];
    const int*   eidx   = (const int*)  d_in[1];
    const float* ew     = (const float*)d_in[2];
    const float* ea     = (const float*)d_in[3];
    const float* mlp_w1 = (const float*)d_in[4];
    const float* mlp_b1 = (const float*)d_in[5];
    const float* mlp_w2 = (const float*)d_in[6];
    const float* mlp_b2 = (const float*)d_in[7];
    const float* lin1_w = (const float*)d_in[8];
    const float* lin2_w = (const float*)d_in[9];
    const float* lin2_b = (const float*)d_in[10];
    const float* lin_w  = (const float*)d_in[11];
    const float* lin_b  = (const float*)d_in[12];
    float* out = (float*)d_out;

    int N = in_sizes[0] / HID;
    int E = in_sizes[2];

    cudaFuncSetAttribute(edge_kernel, cudaFuncAttributeMaxDynamicSharedMemorySize, EDGE_SMEM);
    cudaFuncSetAttribute(lin1_kernel, cudaFuncAttributeMaxDynamicSharedMemorySize, LIN1_SMEM);
    cudaFuncSetAttribute(out_kernel,  cudaFuncAttributeMaxDynamicSharedMemorySize, OUT_SMEM);

    int ntile_n = (N + TN - 1) / TN;

    lin1_kernel<<<ntile_n, 512, LIN1_SMEM>>>(x, lin1_w, N);
    edge_kernel<<<152, 512, EDGE_SMEM>>>(ea, eidx, ew,
                                         mlp_w1, mlp_b1, mlp_w2, mlp_b2, E);
    out_kernel<<<ntile_n, 512, OUT_SMEM>>>(lin2_w, lin2_b, lin_w, lin_b, out, N);
}

// round 13
// speedup vs baseline: 1.3526x; 1.3526x over previous
#include <cuda_runtime.h>
#include <cuda_bf16.h>
#include <cstdint>

#define NN 40000
#define HID 128
#define NF 128
#define NG 50
#define TE 128
#define TN 128

typedef unsigned long long ull;

// device scratch (no allocations allowed)
__device__ float g_h[NN * NF];
__device__ float g_agg[NN * NF];

// ===========================================================================
// common helpers
// ===========================================================================
__device__ __forceinline__ void red2(float* p, float a, float b) {
    asm volatile("red.global.add.v2.f32 [%0], {%1,%2};"
                 :: "l"(p), "f"(a), "f"(b) : "memory");
}
__device__ __forceinline__ float ex2f(float x) {
    float r; asm("ex2.approx.f32 %0, %1;" : "=f"(r) : "f"(x)); return r;
}
__device__ __forceinline__ float lg2f(float x) {
    float r; asm("lg2.approx.f32 %0, %1;" : "=f"(r) : "f"(x)); return r;
}
__device__ __forceinline__ float fcosf(float x) {
    float r; asm("cos.approx.f32 %0, %1;" : "=f"(r) : "f"(x)); return r;
}
__device__ __forceinline__ float sspf(float x) {
    float t = ex2f(-fabsf(x) * 1.4426950408889634f);
    return fmaxf(x, 0.0f) + 0.69314718055994531f * (lg2f(1.0f + t) - 1.0f);
}

// ===========================================================================
// mma.sync helpers (portable; valid on base sm_103 target)
// ===========================================================================
__device__ __forceinline__ uint32_t smem_u32(const void* p) {
    uint32_t a;
    asm("{ .reg .u64 t; cvta.to.shared.u64 t, %1; cvt.u32.u64 %0, t; }"
        : "=r"(a) : "l"(p));
    return a;
}
__device__ __forceinline__ void ldmx4(unsigned* r, uint32_t addr) {
    asm volatile("ldmatrix.sync.aligned.m8n8.x4.shared.b16 {%0,%1,%2,%3}, [%4];"
        : "=r"(r[0]), "=r"(r[1]), "=r"(r[2]), "=r"(r[3]) : "r"(addr));
}
__device__ __forceinline__ void mma16816(float* c, const unsigned* a,
                                         unsigned b0, unsigned b1) {
    asm volatile(
        "mma.sync.aligned.m16n8k16.row.col.f32.bf16.bf16.f32 "
        "{%0,%1,%2,%3}, {%4,%5,%6,%7}, {%8,%9}, {%0,%1,%2,%3};"
        : "+f"(c[0]), "+f"(c[1]), "+f"(c[2]), "+f"(c[3])
        : "r"(a[0]), "r"(a[1]), "r"(a[2]), "r"(a[3]), "r"(b0), "r"(b1));
}
// byte offset of bf16 element (r, c) in a swizzled tile with row stride rs bytes
__device__ __forceinline__ int phy(int r, int c, int rs) {
    return r * rs + ((((c >> 3) ^ (r & 7))) << 4) + ((c & 7) << 1);
}
__device__ __forceinline__ void split_bf16(float v, __nv_bfloat16& h, __nv_bfloat16& lo) {
    h = __float2bfloat16_rn(v);
    lo = __float2bfloat16_rn(v - __bfloat162float(h));
}
// cp.async 16B (sm_80+)
__device__ __forceinline__ void cp16(uint32_t dst, const void* src) {
    asm volatile("cp.async.cg.shared.global [%0], [%1], 16;"
                 :: "r"(dst), "l"(src) : "memory");
}
#define CP_COMMIT() asm volatile("cp.async.commit_group;" ::: "memory")
#define CP_WAIT0()  asm volatile("cp.async.wait_group 0;" ::: "memory")

// warp-level m16 x n64 x (16*KSTEPS) bf16-split GEMM, C += A@W^T
template<int KSTEPS, int RSA, int RSW>
__device__ __forceinline__ void warp_mma(uint32_t aH, uint32_t aL,
                                         uint32_t wH, uint32_t wL,
                                         int m0, int fbase, int lane,
                                         float C[8][4]) {
#pragma unroll
    for (int ks = 0; ks < KSTEPS; ks++) {
        unsigned Ah[4], Al[4];
        int ra = m0 + (lane & 7) + ((lane >> 3) & 1) * 8;
        int ca = 2 * ks + (lane >> 4);
        uint32_t aoff = (uint32_t)(ra * RSA + ((ca ^ (ra & 7)) << 4));
        ldmx4(Ah, aH + aoff);
        ldmx4(Al, aL + aoff);
#pragma unroll
        for (int ntp = 0; ntp < 4; ntp++) {
            int rb = fbase + 16 * ntp + (lane & 7) + (lane >> 4) * 8;
            int cb = 2 * ks + ((lane >> 3) & 1);
            uint32_t boff = (uint32_t)(rb * RSW + ((cb ^ (rb & 7)) << 4));
            unsigned Bh[4], Bl[4];
            ldmx4(Bh, wH + boff);
            ldmx4(Bl, wL + boff);
            int j = 2 * ntp;
            mma16816(C[j], Ah, Bh[0], Bh[1]);
            mma16816(C[j], Al, Bh[0], Bh[1]);
            mma16816(C[j], Ah, Bl[0], Bl[1]);
            mma16816(C[j + 1], Ah, Bh[2], Bh[3]);
            mma16816(C[j + 1], Al, Bh[2], Bh[3]);
            mma16816(C[j + 1], Ah, Bl[2], Bl[3]);
        }
    }
}

// ===========================================================================
// edge kernel smem layout (bytes)
// ===========================================================================
#define O_W1H   0
#define O_W1L   16384
#define O_W2H   32768
#define O_W2L   65536
#define O_A1H   98304
#define O_A1L   114688
#define O_TSH   131072
#define O_TSL   163840
#define O_SC    196608
#define O_SSRC  197120
#define O_SDST  197632
#define O_SB1   198144
#define O_SB2   198656
#define O_RAW   199168
#define EDGE_SMEM (199168 + TE * NG * 4)   // +25600 raw staging = 224768

// ---------------------------------------------------------------------------
// Fused edge kernel on mma.sync tensor cores (bf16 3-product split).
// ea staging is cp.async-pipelined (zero register residency across GEMMs).
// ---------------------------------------------------------------------------
__global__ __launch_bounds__(512, 1)
void edge_kernel(const float* __restrict__ ea,   // [E][50]
                 const int*   __restrict__ eidx, // [2][E]
                 const float* __restrict__ ew,   // [E]
                 const float* __restrict__ w1,   // [128][50]
                 const float* __restrict__ b1,
                 const float* __restrict__ w2,   // [128][128]
                 const float* __restrict__ b2,
                 int E)
{
    extern __shared__ char smem[];
    uint32_t sbase = smem_u32(smem);
    int tid = threadIdx.x;
    int w = tid >> 5, lane = tid & 31;
    int mw = w & 7;          // edge-row warp (16 rows each)
    int nw = w >> 3;         // filter-col warp (64 cols each)
    int g = lane >> 2, t = lane & 3;

    float* sC   = (float*)(smem + O_SC);
    int*   ssrc = (int*)(smem + O_SSRC);
    int*   sdst = (int*)(smem + O_SDST);
    float* sb1  = (float*)(smem + O_SB1);
    float* sb2  = (float*)(smem + O_SB2);
    float* rawf = (float*)(smem + O_RAW);

    // zero W1 + A1 buffers (K padding 50->64 stays zero forever)
    for (int i = tid; i < 4096; i += 512) {
        ((uint32_t*)(smem + O_W1H))[i] = 0; ((uint32_t*)(smem + O_W1L))[i] = 0;
        ((uint32_t*)(smem + O_A1H))[i] = 0; ((uint32_t*)(smem + O_A1L))[i] = 0;
    }
    __syncthreads();

    for (int idx = tid; idx < NF * NG; idx += 512) {
        int f = idx / NG, k = idx - f * NG;
        __nv_bfloat16 h, lo; split_bf16(w1[idx], h, lo);
        int o = phy(f, k, 128);
        *(__nv_bfloat16*)(smem + O_W1H + o) = h;
        *(__nv_bfloat16*)(smem + O_W1L + o) = lo;
    }
    for (int idx = tid; idx < NF * NF; idx += 512) {
        int f = idx >> 7, k = idx & 127;
        __nv_bfloat16 h, lo; split_bf16(w2[idx], h, lo);
        int o = phy(f, k, 256);
        *(__nv_bfloat16*)(smem + O_W2H + o) = h;
        *(__nv_bfloat16*)(smem + O_W2L + o) = lo;
    }
    if (tid < NF) { sb1[tid] = b1[tid]; sb2[tid] = b2[tid]; }

    const uint32_t A1H = sbase + O_A1H, A1L = sbase + O_A1L;
    const uint32_t W1H = sbase + O_W1H, W1L = sbase + O_W1L;
    const uint32_t W2H = sbase + O_W2H, W2L = sbase + O_W2L;
    const uint32_t TSH = sbase + O_TSH, TSL = sbase + O_TSL;
    const uint32_t RAW = sbase + O_RAW;

    int e0r = 16 * mw + g;
    int e1r = e0r + 8;
    int ntiles = (E + TE - 1) / TE;
    const int EANG = E * NG;

    // ---- staging helpers (lambda-free, inline) ----
    // raw cp.async of one tile's ea block: TE*NG floats = 1600 16B chunks
    // metadata prefetch registers (only 3, only tid<TE)
    float pwv = 0.f; int psv = 0, pdv = 0, pok = 0;

    int tile = blockIdx.x;
    if (tile < ntiles) {
        int base = tile * TE * NG;
#pragma unroll
        for (int i = 0; i < 4; i++) {
            int c16 = tid + (i << 9);
            if (c16 < TE * NG / 4) {
                int foff = base + c16 * 4;
                if (foff + 4 <= EANG) cp16(RAW + (uint32_t)(c16 * 16), ea + foff);
                else *(float4*)(rawf + c16 * 4) = make_float4(0.f, 0.f, 0.f, 0.f);
            }
        }
        CP_COMMIT();
        if (tid < TE) {
            int e = tile * TE + tid;
            pok = (e < E);
            if (pok) { pwv = ew[e]; psv = eidx[e]; pdv = eidx[E + e]; }
        }
    }

    for (; tile < ntiles; tile += gridDim.x) {
        CP_WAIT0();
        __syncthreads();   // raw visible to all; prior tile readers of A1/sC done

        // convert raw -> split bf16 A1; write metadata
        for (int idx = tid; idx < TE * NG; idx += 512) {
            int e = idx / NG, k = idx - e * NG;
            __nv_bfloat16 h, lo; split_bf16(rawf[idx], h, lo);
            int o = phy(e, k, 128);
            *(__nv_bfloat16*)(smem + O_A1H + o) = h;
            *(__nv_bfloat16*)(smem + O_A1L + o) = lo;
        }
        if (tid < TE) {
            sC[tid] = pok ? 0.5f * (fcosf(pwv * 0.31415926535897932f) + 1.0f) : 0.f;
            ssrc[tid] = psv;
            sdst[tid] = pdv;
        }
        __syncthreads();

        // kick next tile's staging (overlaps with GEMMs below)
        int nt = tile + gridDim.x;
        if (nt < ntiles) {
            int base = nt * TE * NG;
#pragma unroll
            for (int i = 0; i < 4; i++) {
                int c16 = tid + (i << 9);
                if (c16 < TE * NG / 4) {
                    int foff = base + c16 * 4;
                    if (foff + 4 <= EANG) cp16(RAW + (uint32_t)(c16 * 16), ea + foff);
                    else *(float4*)(rawf + c16 * 4) = make_float4(0.f, 0.f, 0.f, 0.f);
                }
            }
            CP_COMMIT();
            if (tid < TE) {
                int e = nt * TE + tid;
                pok = (e < E);
                if (pok) { pwv = ew[e]; psv = eidx[e]; pdv = eidx[E + e]; }
                else { pwv = 0.f; psv = 0; pdv = 0; }
            }
        }

        int ebase = tile * TE;

        // GEMM1 (K=64 padded: 4 k-steps)
        float C[8][4];
#pragma unroll
        for (int j = 0; j < 8; j++)
#pragma unroll
            for (int q = 0; q < 4; q++) C[j][q] = 0.f;
        warp_mma<4, 128, 128>(A1H, A1L, W1H, W1L, 16 * mw, 64 * nw, lane, C);

        // epilogue1: bias + ssp -> split -> Ts
#pragma unroll
        for (int j = 0; j < 8; j++) {
            int f = 64 * nw + 8 * j + 2 * t;
            float bb0 = sb1[f], bb1 = sb1[f + 1];
            float v00 = sspf(C[j][0] + bb0), v01 = sspf(C[j][1] + bb1);
            float v10 = sspf(C[j][2] + bb0), v11 = sspf(C[j][3] + bb1);
            __nv_bfloat16 h0, l0, h1, l1;
            __nv_bfloat162 hh, ll;
            split_bf16(v00, h0, l0); split_bf16(v01, h1, l1);
            hh.x = h0; hh.y = h1; ll.x = l0; ll.y = l1;
            int o0 = phy(e0r, f, 256);
            *(__nv_bfloat162*)(smem + O_TSH + o0) = hh;
            *(__nv_bfloat162*)(smem + O_TSL + o0) = ll;
            split_bf16(v10, h0, l0); split_bf16(v11, h1, l1);
            hh.x = h0; hh.y = h1; ll.x = l0; ll.y = l1;
            int o1 = phy(e1r, f, 256);
            *(__nv_bfloat162*)(smem + O_TSH + o1) = hh;
            *(__nv_bfloat162*)(smem + O_TSL + o1) = ll;
        }
        __syncthreads();

        // GEMM2 (K=128: 8 k-steps)
#pragma unroll
        for (int j = 0; j < 8; j++)
#pragma unroll
            for (int q = 0; q < 4; q++) C[j][q] = 0.f;
        warp_mma<8, 256, 256>(TSH, TSL, W2H, W2L, 16 * mw, 64 * nw, lane, C);

        // epilogue2: (C + b2) * env * h[src] -> red.v2 agg[dst]
        {
            int ge0 = ebase + e0r, ge1 = ebase + e1r;
            float c0 = sC[e0r], c1 = sC[e1r];
            int s0 = ssrc[e0r], d0 = sdst[e0r];
            int s1 = ssrc[e1r], d1 = sdst[e1r];
#pragma unroll
            for (int j = 0; j < 8; j++) {
                int f = 64 * nw + 8 * j + 2 * t;
                float bb0 = sb2[f], bb1 = sb2[f + 1];
                if (ge0 < E) {
                    float2 h = *(const float2*)(g_h + s0 * NF + f);
                    red2(g_agg + d0 * NF + f,
                         (C[j][0] + bb0) * c0 * h.x,
                         (C[j][1] + bb1) * c0 * h.y);
                }
                if (ge1 < E) {
                    float2 h = *(const float2*)(g_h + s1 * NF + f);
                    red2(g_agg + d1 * NF + f,
                         (C[j][2] + bb0) * c1 * h.x,
                         (C[j][3] + bb1) * c1 * h.y);
                }
            }
        }
    }
}

// ===========================================================================
// lin1 on mma.sync: h = x @ lin1_w^T (no bias); also zeroes g_agg slice.
// smem: WH 0, WL 32768, XH 65536, XL 98304  (131072 bytes)
// ===========================================================================
#define LIN1_SMEM 131072

__global__ __launch_bounds__(512, 1)
void lin1_kernel(const float* __restrict__ x, const float* __restrict__ w, int N) {
    extern __shared__ char smem[];
    uint32_t sbase = smem_u32(smem);
    int tid = threadIdx.x;
    int wp = tid >> 5, lane = tid & 31;
    int mw = wp & 7, nw = wp >> 3;
    int g = lane >> 2, t = lane & 3;

    int nb = blockIdx.x * TN;

    // zero this block's slice of g_agg (replaces zero_agg kernel)
    {
        int zrows = NN - nb; if (zrows > TN) zrows = TN;
        if (zrows > 0) {
            float4* az = (float4*)(g_agg + nb * NF);
            int n4 = zrows * (NF / 4);
            for (int i = tid; i < n4; i += 512)
                az[i] = make_float4(0.f, 0.f, 0.f, 0.f);
        }
    }

    for (int idx = tid; idx < NF * HID; idx += 512) {
        int f = idx >> 7, k = idx & 127;
        __nv_bfloat16 h, lo; split_bf16(w[idx], h, lo);
        int o = phy(f, k, 256);
        *(__nv_bfloat16*)(smem + 0 + o) = h;
        *(__nv_bfloat16*)(smem + 32768 + o) = lo;
    }
    for (int idx = tid; idx < TN * HID; idx += 512) {
        int n = idx >> 7, k = idx & 127;
        float v = (nb + n < N) ? x[(nb + n) * HID + k] : 0.f;
        __nv_bfloat16 h, lo; split_bf16(v, h, lo);
        int o = phy(n, k, 256);
        *(__nv_bfloat16*)(smem + 65536 + o) = h;
        *(__nv_bfloat16*)(smem + 98304 + o) = lo;
    }
    __syncthreads();

    float C[8][4];
#pragma unroll
    for (int j = 0; j < 8; j++)
#pragma unroll
        for (int q = 0; q < 4; q++) C[j][q] = 0.f;
    warp_mma<8, 256, 256>(sbase + 65536, sbase + 98304,
                          sbase + 0, sbase + 32768,
                          16 * mw, 64 * nw, lane, C);

    int r0 = nb + 16 * mw + g, r1 = r0 + 8;
#pragma unroll
    for (int j = 0; j < 8; j++) {
        int f = 64 * nw + 8 * j + 2 * t;
        if (r0 < N) *(float2*)(g_h + r0 * NF + f) = make_float2(C[j][0], C[j][1]);
        if (r1 < N) *(float2*)(g_h + r1 * NF + f) = make_float2(C[j][2], C[j][3]);
    }
}

// ===========================================================================
// out on mma.sync: out = ssp(agg @ lin2^T + b2) @ lin_w^T + bo.
// smem: W2H 0, W2L 32768, WOH 65536, WOL 98304, AH 131072, AL 163840,
//       sb2 196608, sbo 197120   (197632 bytes)
// ===========================================================================
#define OUT_SMEM 197632

__global__ __launch_bounds__(512, 1)
void out_kernel(const float* __restrict__ w2, const float* __restrict__ b2,
                const float* __restrict__ wo, const float* __restrict__ bo,
                float* __restrict__ out, int N)
{
    extern __shared__ char smem[];
    uint32_t sbase = smem_u32(smem);
    int tid = threadIdx.x;
    int wp = tid >> 5, lane = tid & 31;
    int mw = wp & 7, nw = wp >> 3;
    int g = lane >> 2, t = lane & 3;

    float* sb2 = (float*)(smem + 196608);
    float* sbo = (float*)(smem + 197120);

    for (int idx = tid; idx < NF * NF; idx += 512) {
        int f = idx >> 7, k = idx & 127;
        int o = phy(f, k, 256);
        __nv_bfloat16 h, lo;
        split_bf16(w2[idx], h, lo);
        *(__nv_bfloat16*)(smem + 0 + o) = h;
        *(__nv_bfloat16*)(smem + 32768 + o) = lo;
        split_bf16(wo[idx], h, lo);
        *(__nv_bfloat16*)(smem + 65536 + o) = h;
        *(__nv_bfloat16*)(smem + 98304 + o) = lo;
    }
    if (tid < NF) { sb2[tid] = b2[tid]; sbo[tid] = bo[tid]; }

    int nb = blockIdx.x * TN;
    for (int idx = tid; idx < TN * NF; idx += 512) {
        int n = idx >> 7, k = idx & 127;
        float v = (nb + n < N) ? g_agg[(nb + n) * NF + k] : 0.f;
        __nv_bfloat16 h, lo; split_bf16(v, h, lo);
        int o = phy(n, k, 256);
        *(__nv_bfloat16*)(smem + 131072 + o) = h;
        *(__nv_bfloat16*)(smem + 163840 + o) = lo;
    }
    __syncthreads();

    // GEMM1: C = agg @ lin2^T
    float C[8][4];
#pragma unroll
    for (int j = 0; j < 8; j++)
#pragma unroll
        for (int q = 0; q < 4; q++) C[j][q] = 0.f;
    warp_mma<8, 256, 256>(sbase + 131072, sbase + 163840,
                          sbase + 0, sbase + 32768,
                          16 * mw, 64 * nw, lane, C);
    __syncthreads();   // all A reads done before overwrite

    // epilogue: bias + ssp -> split -> back into A buffers (as h2)
    int e0r = 16 * mw + g, e1r = e0r + 8;
#pragma unroll
    for (int j = 0; j < 8; j++) {
        int f = 64 * nw + 8 * j + 2 * t;
        float bb0 = sb2[f], bb1 = sb2[f + 1];
        float v00 = sspf(C[j][0] + bb0), v01 = sspf(C[j][1] + bb1);
        float v10 = sspf(C[j][2] + bb0), v11 = sspf(C[j][3] + bb1);
        __nv_bfloat16 h0, l0, h1, l1;
        __nv_bfloat162 hh, ll;
        split_bf16(v00, h0, l0); split_bf16(v01, h1, l1);
        hh.x = h0; hh.y = h1; ll.x = l0; ll.y = l1;
        int o0 = phy(e0r, f, 256);
        *(__nv_bfloat162*)(smem + 131072 + o0) = hh;
        *(__nv_bfloat162*)(smem + 163840 + o0) = ll;
        split_bf16(v10, h0, l0); split_bf16(v11, h1, l1);
        hh.x = h0; hh.y = h1; ll.x = l0; ll.y = l1;
        int o1 = phy(e1r, f, 256);
        *(__nv_bfloat162*)(smem + 131072 + o1) = hh;
        *(__nv_bfloat162*)(smem + 163840 + o1) = ll;
    }
    __syncthreads();

    // GEMM2: C = h2 @ lin_w^T
#pragma unroll
    for (int j = 0; j < 8; j++)
#pragma unroll
        for (int q = 0; q < 4; q++) C[j][q] = 0.f;
    warp_mma<8, 256, 256>(sbase + 131072, sbase + 163840,
                          sbase + 65536, sbase + 98304,
                          16 * mw, 64 * nw, lane, C);

    int r0 = nb + e0r, r1 = nb + e1r;
#pragma unroll
    for (int j = 0; j < 8; j++) {
        int f = 64 * nw + 8 * j + 2 * t;
        float bb0 = sbo[f], bb1 = sbo[f + 1];
        if (r0 < N)
            *(float2*)(out + r0 * HID + f) = make_float2(C[j][0] + bb0, C[j][1] + bb1);
        if (r1 < N)
            *(float2*)(out + r1 * HID + f) = make_float2(C[j][2] + bb0, C[j][3] + bb1);
    }
}

// ---------------------------------------------------------------------------

extern "C" void kernel_launch(void* const* d_in, const int* in_sizes, int n_in,
                              void* d_out, int out_size) {
    const float* x      = (const float*)d_in[0];
    const int*   eidx   = (const int*)  d_in[1];
    const float* ew     = (const float*)d_in[2];
    const float* ea     = (const float*)d_in[3];
    const float* mlp_w1 = (const float*)d_in[4];
    const float* mlp_b1 = (const float*)d_in[5];
    const float* mlp_w2 = (const float*)d_in[6];
    const float* mlp_b2 = (const float*)d_in[7];
    const float* lin1_w = (const float*)d_in[8];
    const float* lin2_w = (const float*)d_in[9];
    const float* lin2_b = (const float*)d_in[10];
    const float* lin_w  = (const float*)d_in[11];
    const float* lin_b  = (const float*)d_in[12];
    float* out = (float*)d_out;

    int N = in_sizes[0] / HID;
    int E = in_sizes[2];

    cudaFuncSetAttribute(edge_kernel, cudaFuncAttributeMaxDynamicSharedMemorySize, EDGE_SMEM);
    cudaFuncSetAttribute(lin1_kernel, cudaFuncAttributeMaxDynamicSharedMemorySize, LIN1_SMEM);
    cudaFuncSetAttribute(out_kernel,  cudaFuncAttributeMaxDynamicSharedMemorySize, OUT_SMEM);

    int ntile_n = (N + TN - 1) / TN;

    lin1_kernel<<<ntile_n, 512, LIN1_SMEM>>>(x, lin1_w, N);
    edge_kernel<<<152, 512, EDGE_SMEM>>>(ea, eidx, ew,
                                         mlp_w1, mlp_b1, mlp_w2, mlp_b2, E);
    out_kernel<<<ntile_n, 512, OUT_SMEM>>>(lin2_w, lin2_b, lin_w, lin_b, out, N);
}

// round 14
// speedup vs baseline: 1.5415x; 1.1397x over previous
#include <cuda_runtime.h>
#include <cuda_bf16.h>
#include <cstdint>

#define NN 40000
#define HID 128
#define NF 128
#define NG 50
#define TN 128
#define TEH 64          // edges per half-tile

typedef unsigned long long ull;

// device scratch (no allocations allowed)
__device__ float g_h[NN * NF];
__device__ float g_agg[NN * NF];

// ===========================================================================
// common helpers
// ===========================================================================
__device__ __forceinline__ void red2(float* p, float a, float b) {
    asm volatile("red.global.add.v2.f32 [%0], {%1,%2};"
                 :: "l"(p), "f"(a), "f"(b) : "memory");
}
__device__ __forceinline__ float ex2f(float x) {
    float r; asm("ex2.approx.f32 %0, %1;" : "=f"(r) : "f"(x)); return r;
}
__device__ __forceinline__ float lg2f(float x) {
    float r; asm("lg2.approx.f32 %0, %1;" : "=f"(r) : "f"(x)); return r;
}
__device__ __forceinline__ float fcosf(float x) {
    float r; asm("cos.approx.f32 %0, %1;" : "=f"(r) : "f"(x)); return r;
}
__device__ __forceinline__ float sspf(float x) {
    float t = ex2f(-fabsf(x) * 1.4426950408889634f);
    return fmaxf(x, 0.0f) + 0.69314718055994531f * (lg2f(1.0f + t) - 1.0f);
}

// ===========================================================================
// mma.sync helpers (portable; valid on base sm_103 target)
// ===========================================================================
__device__ __forceinline__ uint32_t smem_u32(const void* p) {
    uint32_t a;
    asm("{ .reg .u64 t; cvta.to.shared.u64 t, %1; cvt.u32.u64 %0, t; }"
        : "=r"(a) : "l"(p));
    return a;
}
__device__ __forceinline__ void ldmx4(unsigned* r, uint32_t addr) {
    asm volatile("ldmatrix.sync.aligned.m8n8.x4.shared.b16 {%0,%1,%2,%3}, [%4];"
        : "=r"(r[0]), "=r"(r[1]), "=r"(r[2]), "=r"(r[3]) : "r"(addr));
}
__device__ __forceinline__ void mma16816(float* c, const unsigned* a,
                                         unsigned b0, unsigned b1) {
    asm volatile(
        "mma.sync.aligned.m16n8k16.row.col.f32.bf16.bf16.f32 "
        "{%0,%1,%2,%3}, {%4,%5,%6,%7}, {%8,%9}, {%0,%1,%2,%3};"
        : "+f"(c[0]), "+f"(c[1]), "+f"(c[2]), "+f"(c[3])
        : "r"(a[0]), "r"(a[1]), "r"(a[2]), "r"(a[3]), "r"(b0), "r"(b1));
}
// byte offset of bf16 element (r, c) in a swizzled tile with row stride rs bytes
__device__ __forceinline__ int phy(int r, int c, int rs) {
    return r * rs + ((((c >> 3) ^ (r & 7))) << 4) + ((c & 7) << 1);
}
__device__ __forceinline__ void split_bf16(float v, __nv_bfloat16& h, __nv_bfloat16& lo) {
    h = __float2bfloat16_rn(v);
    lo = __float2bfloat16_rn(v - __bfloat162float(h));
}
// cp.async 16B (sm_80+)
__device__ __forceinline__ void cp16(uint32_t dst, const void* src) {
    asm volatile("cp.async.cg.shared.global [%0], [%1], 16;"
                 :: "r"(dst), "l"(src) : "memory");
}
#define CP_COMMIT() asm volatile("cp.async.commit_group;" ::: "memory")
#define CP_WAIT0()  asm volatile("cp.async.wait_group 0;" ::: "memory")
// per-half named barrier (256 threads); ids 1 and 2
#define HBAR(h) asm volatile("bar.sync %0, 256;" :: "r"(1 + (h)) : "memory")

// warp-level m16 x n64 x (16*KSTEPS) bf16-split GEMM, C += A@W^T
template<int KSTEPS, int RSA, int RSW>
__device__ __forceinline__ void warp_mma(uint32_t aH, uint32_t aL,
                                         uint32_t wH, uint32_t wL,
                                         int m0, int fbase, int lane,
                                         float C[8][4]) {
#pragma unroll
    for (int ks = 0; ks < KSTEPS; ks++) {
        unsigned Ah[4], Al[4];
        int ra = m0 + (lane & 7) + ((lane >> 3) & 1) * 8;
        int ca = 2 * ks + (lane >> 4);
        uint32_t aoff = (uint32_t)(ra * RSA + ((ca ^ (ra & 7)) << 4));
        ldmx4(Ah, aH + aoff);
        ldmx4(Al, aL + aoff);
#pragma unroll
        for (int ntp = 0; ntp < 4; ntp++) {
            int rb = fbase + 16 * ntp + (lane & 7) + (lane >> 4) * 8;
            int cb = 2 * ks + ((lane >> 3) & 1);
            uint32_t boff = (uint32_t)(rb * RSW + ((cb ^ (rb & 7)) << 4));
            unsigned Bh[4], Bl[4];
            ldmx4(Bh, wH + boff);
            ldmx4(Bl, wL + boff);
            int j = 2 * ntp;
            mma16816(C[j], Ah, Bh[0], Bh[1]);
            mma16816(C[j], Al, Bh[0], Bh[1]);
            mma16816(C[j], Ah, Bl[0], Bl[1]);
            mma16816(C[j + 1], Ah, Bh[2], Bh[3]);
            mma16816(C[j + 1], Al, Bh[2], Bh[3]);
            mma16816(C[j + 1], Ah, Bl[2], Bl[3]);
        }
    }
}

// ===========================================================================
// edge kernel smem layout (bytes)
// ===========================================================================
#define O_W1H   0
#define O_W1L   16384
#define O_W2H   32768
#define O_W2L   65536
#define O_SB1   98304
#define O_SB2   98816
#define O_HALF0 99328
// per-half region (62720 bytes):
#define H_A1H   0
#define H_A1L   8192
#define H_TSH   16384
#define H_TSL   32768
#define H_RAW   49152
#define H_SC    61952
#define H_SSRC  62208
#define H_SDST  62464
#define HALF_SZ 62720
#define EDGE_SMEM (O_HALF0 + 2 * HALF_SZ)   // 224768

// ---------------------------------------------------------------------------
// Fused edge kernel: two independent 256-thread pipelines per block, each
// processing 64-edge tiles with its own buffers + named barriers. The halves'
// phases (tensor / MUFU-ssp / atomics / staging) dephase and overlap.
// ---------------------------------------------------------------------------
__global__ __launch_bounds__(512, 1)
void edge_kernel(const float* __restrict__ ea,   // [E][50]
                 const int*   __restrict__ eidx, // [2][E]
                 const float* __restrict__ ew,   // [E]
                 const float* __restrict__ w1,   // [128][50]
                 const float* __restrict__ b1,
                 const float* __restrict__ w2,   // [128][128]
                 const float* __restrict__ b2,
                 int E)
{
    extern __shared__ char smem[];
    uint32_t sbase = smem_u32(smem);
    int tid = threadIdx.x;
    int half = tid >> 8;          // 0 / 1
    int tidh = tid & 255;
    int wh = tidh >> 5;           // warp within half: 0..7
    int lane = tid & 31;
    int mw = wh & 3;              // 16-edge row group (4 x 16 = 64)
    int nw = wh >> 2;             // 64-filter col group (2 x 64 = 128)
    int g = lane >> 2, t = lane & 3;

    char* hs = smem + O_HALF0 + half * HALF_SZ;
    uint32_t hb = sbase + O_HALF0 + half * HALF_SZ;
    float* rawf = (float*)(hs + H_RAW);
    float* sC   = (float*)(hs + H_SC);
    int*   ssrc = (int*)(hs + H_SSRC);
    int*   sdst = (int*)(hs + H_SDST);
    float* sb1  = (float*)(smem + O_SB1);
    float* sb2  = (float*)(smem + O_SB2);

    // ---- init (full block): zero A1 pads, load split weights ----
    for (int h = 0; h < 2; h++) {
        uint32_t* a1 = (uint32_t*)(smem + O_HALF0 + h * HALF_SZ + H_A1H);
        for (int i = tid; i < 4096; i += 512) a1[i] = 0;   // A1H+A1L (16KB)
    }
    __syncthreads();   // zeros visible before split stores below

    for (int idx = tid; idx < NF * NG; idx += 512) {
        int f = idx / NG, k = idx - f * NG;
        __nv_bfloat16 h, lo; split_bf16(w1[idx], h, lo);
        int o = phy(f, k, 128);
        *(__nv_bfloat16*)(smem + O_W1H + o) = h;
        *(__nv_bfloat16*)(smem + O_W1L + o) = lo;
    }
    for (int idx = tid; idx < NF * NF; idx += 512) {
        int f = idx >> 7, k = idx & 127;
        __nv_bfloat16 h, lo; split_bf16(w2[idx], h, lo);
        int o = phy(f, k, 256);
        *(__nv_bfloat16*)(smem + O_W2H + o) = h;
        *(__nv_bfloat16*)(smem + O_W2L + o) = lo;
    }
    if (tid < NF) { sb1[tid] = b1[tid]; sb2[tid] = b2[tid]; }
    __syncthreads();   // last full-block sync; halves diverge below

    const uint32_t A1H = hb + H_A1H, A1L = hb + H_A1L;
    const uint32_t TSH = hb + H_TSH, TSL = hb + H_TSL;
    const uint32_t RAW = hb + H_RAW;
    const uint32_t W1H = sbase + O_W1H, W1L = sbase + O_W1L;
    const uint32_t W2H = sbase + O_W2H, W2L = sbase + O_W2L;

    int e0r = 16 * mw + g;        // 0..63
    int e1r = e0r + 8;
    const int EANG = E * NG;
    const int CHUNKS = TEH * NG / 4;   // 800 x 16B per half-tile

    int nht = (E + TEH - 1) / TEH;
    int hstep = gridDim.x * 2;
    int ht = blockIdx.x * 2 + half;

    float pwv = 0.f; int psv = 0, pdv = 0, pok = 0;
    if (ht < nht) {
        int base = ht * TEH * NG;
#pragma unroll
        for (int i = 0; i < 4; i++) {
            int c16 = tidh + (i << 8);
            if (c16 < CHUNKS) {
                int foff = base + c16 * 4;
                if (foff + 4 <= EANG) cp16(RAW + (uint32_t)(c16 * 16), ea + foff);
                else *(float4*)(rawf + c16 * 4) = make_float4(0.f, 0.f, 0.f, 0.f);
            }
        }
        CP_COMMIT();
        if (tidh < TEH) {
            int e = ht * TEH + tidh;
            pok = (e < E);
            if (pok) { pwv = ew[e]; psv = eidx[e]; pdv = eidx[E + e]; }
        }
    }

    for (; ht < nht; ht += hstep) {
        CP_WAIT0();
        HBAR(half);   // raw visible; prior tile's readers of A1/Ts/sC done

        // convert raw -> split bf16 A1; write metadata
        for (int idx = tidh; idx < TEH * NG; idx += 256) {
            int e = idx / NG, k = idx - e * NG;
            __nv_bfloat16 h, lo; split_bf16(rawf[idx], h, lo);
            int o = phy(e, k, 128);
            *(__nv_bfloat16*)(hs + H_A1H + o) = h;
            *(__nv_bfloat16*)(hs + H_A1L + o) = lo;
        }
        if (tidh < TEH) {
            sC[tidh] = pok ? 0.5f * (fcosf(pwv * 0.31415926535897932f) + 1.0f) : 0.f;
            ssrc[tidh] = psv;
            sdst[tidh] = pdv;
        }
        HBAR(half);

        // kick next half-tile's staging (overlaps with GEMMs below)
        int nt = ht + hstep;
        if (nt < nht) {
            int base = nt * TEH * NG;
#pragma unroll
            for (int i = 0; i < 4; i++) {
                int c16 = tidh + (i << 8);
                if (c16 < CHUNKS) {
                    int foff = base + c16 * 4;
                    if (foff + 4 <= EANG) cp16(RAW + (uint32_t)(c16 * 16), ea + foff);
                    else *(float4*)(rawf + c16 * 4) = make_float4(0.f, 0.f, 0.f, 0.f);
                }
            }
            CP_COMMIT();
            if (tidh < TEH) {
                int e = nt * TEH + tidh;
                pok = (e < E);
                if (pok) { pwv = ew[e]; psv = eidx[e]; pdv = eidx[E + e]; }
                else { pwv = 0.f; psv = 0; pdv = 0; }
            }
        }

        int ebase = ht * TEH;

        // GEMM1 (K=64 padded: 4 k-steps)
        float C[8][4];
#pragma unroll
        for (int j = 0; j < 8; j++)
#pragma unroll
            for (int q = 0; q < 4; q++) C[j][q] = 0.f;
        warp_mma<4, 128, 128>(A1H, A1L, W1H, W1L, 16 * mw, 64 * nw, lane, C);

        // epilogue1: bias + ssp -> split -> Ts
#pragma unroll
        for (int j = 0; j < 8; j++) {
            int f = 64 * nw + 8 * j + 2 * t;
            float bb0 = sb1[f], bb1 = sb1[f + 1];
            float v00 = sspf(C[j][0] + bb0), v01 = sspf(C[j][1] + bb1);
            float v10 = sspf(C[j][2] + bb0), v11 = sspf(C[j][3] + bb1);
            __nv_bfloat16 h0, l0, h1, l1;
            __nv_bfloat162 hh, ll;
            split_bf16(v00, h0, l0); split_bf16(v01, h1, l1);
            hh.x = h0; hh.y = h1; ll.x = l0; ll.y = l1;
            int o0 = phy(e0r, f, 256);
            *(__nv_bfloat162*)(hs + H_TSH + o0) = hh;
            *(__nv_bfloat162*)(hs + H_TSL + o0) = ll;
            split_bf16(v10, h0, l0); split_bf16(v11, h1, l1);
            hh.x = h0; hh.y = h1; ll.x = l0; ll.y = l1;
            int o1 = phy(e1r, f, 256);
            *(__nv_bfloat162*)(hs + H_TSH + o1) = hh;
            *(__nv_bfloat162*)(hs + H_TSL + o1) = ll;
        }
        HBAR(half);

        // GEMM2 (K=128: 8 k-steps)
#pragma unroll
        for (int j = 0; j < 8; j++)
#pragma unroll
            for (int q = 0; q < 4; q++) C[j][q] = 0.f;
        warp_mma<8, 256, 256>(TSH, TSL, W2H, W2L, 16 * mw, 64 * nw, lane, C);

        // epilogue2: (C + b2) * env * h[src] -> red.v2 agg[dst]
        {
            int ge0 = ebase + e0r, ge1 = ebase + e1r;
            float c0 = sC[e0r], c1 = sC[e1r];
            int s0 = ssrc[e0r], d0 = sdst[e0r];
            int s1 = ssrc[e1r], d1 = sdst[e1r];
#pragma unroll
            for (int j = 0; j < 8; j++) {
                int f = 64 * nw + 8 * j + 2 * t;
                float bb0 = sb2[f], bb1 = sb2[f + 1];
                if (ge0 < E) {
                    float2 h = *(const float2*)(g_h + s0 * NF + f);
                    red2(g_agg + d0 * NF + f,
                         (C[j][0] + bb0) * c0 * h.x,
                         (C[j][1] + bb1) * c0 * h.y);
                }
                if (ge1 < E) {
                    float2 h = *(const float2*)(g_h + s1 * NF + f);
                    red2(g_agg + d1 * NF + f,
                         (C[j][2] + bb0) * c1 * h.x,
                         (C[j][3] + bb1) * c1 * h.y);
                }
            }
        }
    }
}

// ===========================================================================
// lin1 on mma.sync: h = x @ lin1_w^T (no bias); also zeroes g_agg slice.
// smem: WH 0, WL 32768, XH 65536, XL 98304  (131072 bytes)
// ===========================================================================
#define LIN1_SMEM 131072

__global__ __launch_bounds__(512, 1)
void lin1_kernel(const float* __restrict__ x, const float* __restrict__ w, int N) {
    extern __shared__ char smem[];
    uint32_t sbase = smem_u32(smem);
    int tid = threadIdx.x;
    int wp = tid >> 5, lane = tid & 31;
    int mw = wp & 7, nw = wp >> 3;
    int g = lane >> 2, t = lane & 3;

    int nb = blockIdx.x * TN;

    // zero this block's slice of g_agg (replaces zero_agg kernel)
    {
        int zrows = NN - nb; if (zrows > TN) zrows = TN;
        if (zrows > 0) {
            float4* az = (float4*)(g_agg + nb * NF);
            int n4 = zrows * (NF / 4);
            for (int i = tid; i < n4; i += 512)
                az[i] = make_float4(0.f, 0.f, 0.f, 0.f);
        }
    }

    for (int idx = tid; idx < NF * HID; idx += 512) {
        int f = idx >> 7, k = idx & 127;
        __nv_bfloat16 h, lo; split_bf16(w[idx], h, lo);
        int o = phy(f, k, 256);
        *(__nv_bfloat16*)(smem + 0 + o) = h;
        *(__nv_bfloat16*)(smem + 32768 + o) = lo;
    }
    for (int idx = tid; idx < TN * HID; idx += 512) {
        int n = idx >> 7, k = idx & 127;
        float v = (nb + n < N) ? x[(nb + n) * HID + k] : 0.f;
        __nv_bfloat16 h, lo; split_bf16(v, h, lo);
        int o = phy(n, k, 256);
        *(__nv_bfloat16*)(smem + 65536 + o) = h;
        *(__nv_bfloat16*)(smem + 98304 + o) = lo;
    }
    __syncthreads();

    float C[8][4];
#pragma unroll
    for (int j = 0; j < 8; j++)
#pragma unroll
        for (int q = 0; q < 4; q++) C[j][q] = 0.f;
    warp_mma<8, 256, 256>(sbase + 65536, sbase + 98304,
                          sbase + 0, sbase + 32768,
                          16 * mw, 64 * nw, lane, C);

    int r0 = nb + 16 * mw + g, r1 = r0 + 8;
#pragma unroll
    for (int j = 0; j < 8; j++) {
        int f = 64 * nw + 8 * j + 2 * t;
        if (r0 < N) *(float2*)(g_h + r0 * NF + f) = make_float2(C[j][0], C[j][1]);
        if (r1 < N) *(float2*)(g_h + r1 * NF + f) = make_float2(C[j][2], C[j][3]);
    }
}

// ===========================================================================
// out on mma.sync: out = ssp(agg @ lin2^T + b2) @ lin_w^T + bo.
// smem: W2H 0, W2L 32768, WOH 65536, WOL 98304, AH 131072, AL 163840,
//       sb2 196608, sbo 197120   (197632 bytes)
// ===========================================================================
#define OUT_SMEM 197632

__global__ __launch_bounds__(512, 1)
void out_kernel(const float* __restrict__ w2, const float* __restrict__ b2,
                const float* __restrict__ wo, const float* __restrict__ bo,
                float* __restrict__ out, int N)
{
    extern __shared__ char smem[];
    uint32_t sbase = smem_u32(smem);
    int tid = threadIdx.x;
    int wp = tid >> 5, lane = tid & 31;
    int mw = wp & 7, nw = wp >> 3;
    int g = lane >> 2, t = lane & 3;

    float* sb2 = (float*)(smem + 196608);
    float* sbo = (float*)(smem + 197120);

    for (int idx = tid; idx < NF * NF; idx += 512) {
        int f = idx >> 7, k = idx & 127;
        int o = phy(f, k, 256);
        __nv_bfloat16 h, lo;
        split_bf16(w2[idx], h, lo);
        *(__nv_bfloat16*)(smem + 0 + o) = h;
        *(__nv_bfloat16*)(smem + 32768 + o) = lo;
        split_bf16(wo[idx], h, lo);
        *(__nv_bfloat16*)(smem + 65536 + o) = h;
        *(__nv_bfloat16*)(smem + 98304 + o) = lo;
    }
    if (tid < NF) { sb2[tid] = b2[tid]; sbo[tid] = bo[tid]; }

    int nb = blockIdx.x * TN;
    for (int idx = tid; idx < TN * NF; idx += 512) {
        int n = idx >> 7, k = idx & 127;
        float v = (nb + n < N) ? g_agg[(nb + n) * NF + k] : 0.f;
        __nv_bfloat16 h, lo; split_bf16(v, h, lo);
        int o = phy(n, k, 256);
        *(__nv_bfloat16*)(smem + 131072 + o) = h;
        *(__nv_bfloat16*)(smem + 163840 + o) = lo;
    }
    __syncthreads();

    // GEMM1: C = agg @ lin2^T
    float C[8][4];
#pragma unroll
    for (int j = 0; j < 8; j++)
#pragma unroll
        for (int q = 0; q < 4; q++) C[j][q] = 0.f;
    warp_mma<8, 256, 256>(sbase + 131072, sbase + 163840,
                          sbase + 0, sbase + 32768,
                          16 * mw, 64 * nw, lane, C);
    __syncthreads();   // all A reads done before overwrite

    // epilogue: bias + ssp -> split -> back into A buffers (as h2)
    int e0r = 16 * mw + g, e1r = e0r + 8;
#pragma unroll
    for (int j = 0; j < 8; j++) {
        int f = 64 * nw + 8 * j + 2 * t;
        float bb0 = sb2[f], bb1 = sb2[f + 1];
        float v00 = sspf(C[j][0] + bb0), v01 = sspf(C[j][1] + bb1);
        float v10 = sspf(C[j][2] + bb0), v11 = sspf(C[j][3] + bb1);
        __nv_bfloat16 h0, l0, h1, l1;
        __nv_bfloat162 hh, ll;
        split_bf16(v00, h0, l0); split_bf16(v01, h1, l1);
        hh.x = h0; hh.y = h1; ll.x = l0; ll.y = l1;
        int o0 = phy(e0r, f, 256);
        *(__nv_bfloat162*)(smem + 131072 + o0) = hh;
        *(__nv_bfloat162*)(smem + 163840 + o0) = ll;
        split_bf16(v10, h0, l0); split_bf16(v11, h1, l1);
        hh.x = h0; hh.y = h1; ll.x = l0; ll.y = l1;
        int o1 = phy(e1r, f, 256);
        *(__nv_bfloat162*)(smem + 131072 + o1) = hh;
        *(__nv_bfloat162*)(smem + 163840 + o1) = ll;
    }
    __syncthreads();

    // GEMM2: C = h2 @ lin_w^T
#pragma unroll
    for (int j = 0; j < 8; j++)
#pragma unroll
        for (int q = 0; q < 4; q++) C[j][q] = 0.f;
    warp_mma<8, 256, 256>(sbase + 131072, sbase + 163840,
                          sbase + 65536, sbase + 98304,
                          16 * mw, 64 * nw, lane, C);

    int r0 = nb + e0r, r1 = nb + e1r;
#pragma unroll
    for (int j = 0; j < 8; j++) {
        int f = 64 * nw + 8 * j + 2 * t;
        float bb0 = sbo[f], bb1 = sbo[f + 1];
        if (r0 < N)
            *(float2*)(out + r0 * HID + f) = make_float2(C[j][0] + bb0, C[j][1] + bb1);
        if (r1 < N)
            *(float2*)(out + r1 * HID + f) = make_float2(C[j][2] + bb0, C[j][3] + bb1);
    }
}

// ---------------------------------------------------------------------------

extern "C" void kernel_launch(void* const* d_in, const int* in_sizes, int n_in,
                              void* d_out, int out_size) {
    const float* x      = (const float*)d_in[0];
    const int*   eidx   = (const int*)  d_in[1];
    const float* ew     = (const float*)d_in[2];
    const float* ea     = (const float*)d_in[3];
    const float* mlp_w1 = (const float*)d_in[4];
    const float* mlp_b1 = (const float*)d_in[5];
    const float* mlp_w2 = (const float*)d_in[6];
    const float* mlp_b2 = (const float*)d_in[7];
    const float* lin1_w = (const float*)d_in[8];
    const float* lin2_w = (const float*)d_in[9];
    const float* lin2_b = (const float*)d_in[10];
    const float* lin_w  = (const float*)d_in[11];
    const float* lin_b  = (const float*)d_in[12];
    float* out = (float*)d_out;

    int N = in_sizes[0] / HID;
    int E = in_sizes[2];

    cudaFuncSetAttribute(edge_kernel, cudaFuncAttributeMaxDynamicSharedMemorySize, EDGE_SMEM);
    cudaFuncSetAttribute(lin1_kernel, cudaFuncAttributeMaxDynamicSharedMemorySize, LIN1_SMEM);
    cudaFuncSetAttribute(out_kernel,  cudaFuncAttributeMaxDynamicSharedMemorySize, OUT_SMEM);

    int ntile_n = (N + TN - 1) / TN;

    lin1_kernel<<<ntile_n, 512, LIN1_SMEM>>>(x, lin1_w, N);
    edge_kernel<<<152, 512, EDGE_SMEM>>>(ea, eidx, ew,
                                         mlp_w1, mlp_b1, mlp_w2, mlp_b2, E);
    out_kernel<<<ntile_n, 512, OUT_SMEM>>>(lin2_w, lin2_b, lin_w, lin_b, out, N);
}

// round 15
// speedup vs baseline: 1.5488x; 1.0048x over previous
#include <cuda_runtime.h>
#include <cuda_bf16.h>
#include <cstdint>

#define NN 40000
#define HID 128
#define NF 128
#define NG 50
#define TN 128
#define TEQ 32          // edges per quarter-tile

typedef unsigned long long ull;

// device scratch (no allocations allowed)
__device__ float g_h[NN * NF];
__device__ float g_agg[NN * NF];

// ===========================================================================
// common helpers
// ===========================================================================
__device__ __forceinline__ void red2(float* p, float a, float b) {
    asm volatile("red.global.add.v2.f32 [%0], {%1,%2};"
                 :: "l"(p), "f"(a), "f"(b) : "memory");
}
__device__ __forceinline__ float ex2f(float x) {
    float r; asm("ex2.approx.f32 %0, %1;" : "=f"(r) : "f"(x)); return r;
}
__device__ __forceinline__ float lg2f(float x) {
    float r; asm("lg2.approx.f32 %0, %1;" : "=f"(r) : "f"(x)); return r;
}
__device__ __forceinline__ float fcosf(float x) {
    float r; asm("cos.approx.f32 %0, %1;" : "=f"(r) : "f"(x)); return r;
}
__device__ __forceinline__ float sspf(float x) {
    float t = ex2f(-fabsf(x) * 1.4426950408889634f);
    return fmaxf(x, 0.0f) + 0.69314718055994531f * (lg2f(1.0f + t) - 1.0f);
}

// ===========================================================================
// mma.sync helpers (portable; valid on base sm_103 target)
// ===========================================================================
__device__ __forceinline__ uint32_t smem_u32(const void* p) {
    uint32_t a;
    asm("{ .reg .u64 t; cvta.to.shared.u64 t, %1; cvt.u32.u64 %0, t; }"
        : "=r"(a) : "l"(p));
    return a;
}
__device__ __forceinline__ void ldmx4(unsigned* r, uint32_t addr) {
    asm volatile("ldmatrix.sync.aligned.m8n8.x4.shared.b16 {%0,%1,%2,%3}, [%4];"
        : "=r"(r[0]), "=r"(r[1]), "=r"(r[2]), "=r"(r[3]) : "r"(addr));
}
__device__ __forceinline__ void mma16816(float* c, const unsigned* a,
                                         unsigned b0, unsigned b1) {
    asm volatile(
        "mma.sync.aligned.m16n8k16.row.col.f32.bf16.bf16.f32 "
        "{%0,%1,%2,%3}, {%4,%5,%6,%7}, {%8,%9}, {%0,%1,%2,%3};"
        : "+f"(c[0]), "+f"(c[1]), "+f"(c[2]), "+f"(c[3])
        : "r"(a[0]), "r"(a[1]), "r"(a[2]), "r"(a[3]), "r"(b0), "r"(b1));
}
// byte offset of bf16 element (r, c) in a swizzled tile with row stride rs bytes
__device__ __forceinline__ int phy(int r, int c, int rs) {
    return r * rs + ((((c >> 3) ^ (r & 7))) << 4) + ((c & 7) << 1);
}
__device__ __forceinline__ void split_bf16(float v, __nv_bfloat16& h, __nv_bfloat16& lo) {
    h = __float2bfloat16_rn(v);
    lo = __float2bfloat16_rn(v - __bfloat162float(h));
}
// cp.async 16B (sm_80+)
__device__ __forceinline__ void cp16(uint32_t dst, const void* src) {
    asm volatile("cp.async.cg.shared.global [%0], [%1], 16;"
                 :: "r"(dst), "l"(src) : "memory");
}
#define CP_COMMIT() asm volatile("cp.async.commit_group;" ::: "memory")
#define CP_WAIT0()  asm volatile("cp.async.wait_group 0;" ::: "memory")
// per-quarter named barrier (128 threads); ids 1..4
#define QBAR(q) asm volatile("bar.sync %0, 128;" :: "r"(1 + (q)) : "memory")

// warp-level m16 x n64 x (16*KSTEPS) bf16-split GEMM, C += A@W^T
template<int KSTEPS, int RSA, int RSW>
__device__ __forceinline__ void warp_mma(uint32_t aH, uint32_t aL,
                                         uint32_t wH, uint32_t wL,
                                         int m0, int fbase, int lane,
                                         float C[8][4]) {
#pragma unroll
    for (int ks = 0; ks < KSTEPS; ks++) {
        unsigned Ah[4], Al[4];
        int ra = m0 + (lane & 7) + ((lane >> 3) & 1) * 8;
        int ca = 2 * ks + (lane >> 4);
        uint32_t aoff = (uint32_t)(ra * RSA + ((ca ^ (ra & 7)) << 4));
        ldmx4(Ah, aH + aoff);
        ldmx4(Al, aL + aoff);
#pragma unroll
        for (int ntp = 0; ntp < 4; ntp++) {
            int rb = fbase + 16 * ntp + (lane & 7) + (lane >> 4) * 8;
            int cb = 2 * ks + ((lane >> 3) & 1);
            uint32_t boff = (uint32_t)(rb * RSW + ((cb ^ (rb & 7)) << 4));
            unsigned Bh[4], Bl[4];
            ldmx4(Bh, wH + boff);
            ldmx4(Bl, wL + boff);
            int j = 2 * ntp;
            mma16816(C[j], Ah, Bh[0], Bh[1]);
            mma16816(C[j], Al, Bh[0], Bh[1]);
            mma16816(C[j], Ah, Bl[0], Bl[1]);
            mma16816(C[j + 1], Ah, Bh[2], Bh[3]);
            mma16816(C[j + 1], Al, Bh[2], Bh[3]);
            mma16816(C[j + 1], Ah, Bl[2], Bl[3]);
        }
    }
}

// ===========================================================================
// edge kernel smem layout (bytes)
// ===========================================================================
#define O_W1H   0
#define O_W1L   16384
#define O_W2H   32768
#define O_W2L   65536
#define O_SB1   98304
#define O_SB2   98816
#define O_QTR0  99328
// per-quarter region (31360 bytes):
#define Q_A1H   0
#define Q_A1L   4096
#define Q_TSH   8192
#define Q_TSL   16384
#define Q_RAW   24576
#define Q_SC    30976
#define Q_SSRC  31104
#define Q_SDST  31232
#define QTR_SZ  31360
#define EDGE_SMEM (O_QTR0 + 4 * QTR_SZ)   // 224768

// ---------------------------------------------------------------------------
// Fused edge kernel: FOUR independent 128-thread pipelines per block, each
// processing 32-edge tiles with its own buffers + named barrier. Each SMSP
// hosts exactly one warp from each quarter, so independently-phased pipelines
// keep all pipes (tensor/MUFU/LSU/atomic) fed.
// ---------------------------------------------------------------------------
__global__ __launch_bounds__(512, 1)
void edge_kernel(const float* __restrict__ ea,   // [E][50]
                 const int*   __restrict__ eidx, // [2][E]
                 const float* __restrict__ ew,   // [E]
                 const float* __restrict__ w1,   // [128][50]
                 const float* __restrict__ b1,
                 const float* __restrict__ w2,   // [128][128]
                 const float* __restrict__ b2,
                 int E)
{
    extern __shared__ char smem[];
    uint32_t sbase = smem_u32(smem);
    int tid = threadIdx.x;
    int q = tid >> 7;             // quarter 0..3
    int tidq = tid & 127;
    int wq = tidq >> 5;           // warp within quarter: 0..3
    int lane = tid & 31;
    int mw = wq & 1;              // 16-edge row group (2 x 16 = 32)
    int nw = wq >> 1;             // 64-filter col group (2 x 64 = 128)
    int g = lane >> 2, t = lane & 3;

    char* qs = smem + O_QTR0 + q * QTR_SZ;
    uint32_t qb = sbase + O_QTR0 + q * QTR_SZ;
    float* rawf = (float*)(qs + Q_RAW);
    float* sC   = (float*)(qs + Q_SC);
    int*   ssrc = (int*)(qs + Q_SSRC);
    int*   sdst = (int*)(qs + Q_SDST);
    float* sb1  = (float*)(smem + O_SB1);
    float* sb2  = (float*)(smem + O_SB2);

    // ---- init (full block): zero A1 pads in all quarters, load split weights
    {
        uint32_t* a1 = (uint32_t*)(smem + O_QTR0);
        // zero A1H+A1L (8KB) of each quarter: strided over the 4 regions
        for (int h = 0; h < 4; h++) {
            uint32_t* p = (uint32_t*)(smem + O_QTR0 + h * QTR_SZ + Q_A1H);
            for (int i = tid; i < 2048; i += 512) p[i] = 0;
        }
        (void)a1;
    }
    __syncthreads();

    for (int idx = tid; idx < NF * NG; idx += 512) {
        int f = idx / NG, k = idx - f * NG;
        __nv_bfloat16 h, lo; split_bf16(w1[idx], h, lo);
        int o = phy(f, k, 128);
        *(__nv_bfloat16*)(smem + O_W1H + o) = h;
        *(__nv_bfloat16*)(smem + O_W1L + o) = lo;
    }
    for (int idx = tid; idx < NF * NF; idx += 512) {
        int f = idx >> 7, k = idx & 127;
        __nv_bfloat16 h, lo; split_bf16(w2[idx], h, lo);
        int o = phy(f, k, 256);
        *(__nv_bfloat16*)(smem + O_W2H + o) = h;
        *(__nv_bfloat16*)(smem + O_W2L + o) = lo;
    }
    if (tid < NF) { sb1[tid] = b1[tid]; sb2[tid] = b2[tid]; }
    __syncthreads();   // last full-block sync; quarters diverge below

    const uint32_t A1H = qb + Q_A1H, A1L = qb + Q_A1L;
    const uint32_t TSH = qb + Q_TSH, TSL = qb + Q_TSL;
    const uint32_t RAW = qb + Q_RAW;
    const uint32_t W1H = sbase + O_W1H, W1L = sbase + O_W1L;
    const uint32_t W2H = sbase + O_W2H, W2L = sbase + O_W2L;

    int e0r = 16 * mw + g;        // 0..31
    int e1r = e0r + 8;
    const int EANG = E * NG;
    const int CHUNKS = TEQ * NG / 4;   // 400 x 16B per quarter-tile

    int nqt = (E + TEQ - 1) / TEQ;
    int qstep = gridDim.x * 4;
    int qt = blockIdx.x * 4 + q;

    float pwv = 0.f; int psv = 0, pdv = 0, pok = 0;
    if (qt < nqt) {
        int base = qt * TEQ * NG;
#pragma unroll
        for (int i = 0; i < 4; i++) {
            int c16 = tidq + (i << 7);
            if (c16 < CHUNKS) {
                int foff = base + c16 * 4;
                if (foff + 4 <= EANG) cp16(RAW + (uint32_t)(c16 * 16), ea + foff);
                else *(float4*)(rawf + c16 * 4) = make_float4(0.f, 0.f, 0.f, 0.f);
            }
        }
        CP_COMMIT();
        if (tidq < TEQ) {
            int e = qt * TEQ + tidq;
            pok = (e < E);
            if (pok) { pwv = ew[e]; psv = eidx[e]; pdv = eidx[E + e]; }
        }
    }

    for (; qt < nqt; qt += qstep) {
        CP_WAIT0();
        QBAR(q);   // raw visible; prior tile's readers of A1/Ts/sC done

        // convert raw -> split bf16 A1; write metadata
        for (int idx = tidq; idx < TEQ * NG; idx += 128) {
            int e = idx / NG, k = idx - e * NG;
            __nv_bfloat16 h, lo; split_bf16(rawf[idx], h, lo);
            int o = phy(e, k, 128);
            *(__nv_bfloat16*)(qs + Q_A1H + o) = h;
            *(__nv_bfloat16*)(qs + Q_A1L + o) = lo;
        }
        if (tidq < TEQ) {
            sC[tidq] = pok ? 0.5f * (fcosf(pwv * 0.31415926535897932f) + 1.0f) : 0.f;
            ssrc[tidq] = psv;
            sdst[tidq] = pdv;
        }
        QBAR(q);

        // kick next quarter-tile's staging (overlaps with GEMMs below)
        int nt = qt + qstep;
        if (nt < nqt) {
            int base = nt * TEQ * NG;
#pragma unroll
            for (int i = 0; i < 4; i++) {
                int c16 = tidq + (i << 7);
                if (c16 < CHUNKS) {
                    int foff = base + c16 * 4;
                    if (foff + 4 <= EANG) cp16(RAW + (uint32_t)(c16 * 16), ea + foff);
                    else *(float4*)(rawf + c16 * 4) = make_float4(0.f, 0.f, 0.f, 0.f);
                }
            }
            CP_COMMIT();
            if (tidq < TEQ) {
                int e = nt * TEQ + tidq;
                pok = (e < E);
                if (pok) { pwv = ew[e]; psv = eidx[e]; pdv = eidx[E + e]; }
                else { pwv = 0.f; psv = 0; pdv = 0; }
            }
        }

        int ebase = qt * TEQ;

        // GEMM1 (K=64 padded: 4 k-steps)
        float C[8][4];
#pragma unroll
        for (int j = 0; j < 8; j++)
#pragma unroll
            for (int qq = 0; qq < 4; qq++) C[j][qq] = 0.f;
        warp_mma<4, 128, 128>(A1H, A1L, W1H, W1L, 16 * mw, 64 * nw, lane, C);

        // epilogue1: bias + ssp -> split -> Ts
#pragma unroll
        for (int j = 0; j < 8; j++) {
            int f = 64 * nw + 8 * j + 2 * t;
            float bb0 = sb1[f], bb1 = sb1[f + 1];
            float v00 = sspf(C[j][0] + bb0), v01 = sspf(C[j][1] + bb1);
            float v10 = sspf(C[j][2] + bb0), v11 = sspf(C[j][3] + bb1);
            __nv_bfloat16 h0, l0, h1, l1;
            __nv_bfloat162 hh, ll;
            split_bf16(v00, h0, l0); split_bf16(v01, h1, l1);
            hh.x = h0; hh.y = h1; ll.x = l0; ll.y = l1;
            int o0 = phy(e0r, f, 256);
            *(__nv_bfloat162*)(qs + Q_TSH + o0) = hh;
            *(__nv_bfloat162*)(qs + Q_TSL + o0) = ll;
            split_bf16(v10, h0, l0); split_bf16(v11, h1, l1);
            hh.x = h0; hh.y = h1; ll.x = l0; ll.y = l1;
            int o1 = phy(e1r, f, 256);
            *(__nv_bfloat162*)(qs + Q_TSH + o1) = hh;
            *(__nv_bfloat162*)(qs + Q_TSL + o1) = ll;
        }
        QBAR(q);

        // GEMM2 (K=128: 8 k-steps)
#pragma unroll
        for (int j = 0; j < 8; j++)
#pragma unroll
            for (int qq = 0; qq < 4; qq++) C[j][qq] = 0.f;
        warp_mma<8, 256, 256>(TSH, TSL, W2H, W2L, 16 * mw, 64 * nw, lane, C);

        // epilogue2: (C + b2) * env * h[src] -> red.v2 agg[dst]
        {
            int ge0 = ebase + e0r, ge1 = ebase + e1r;
            float c0 = sC[e0r], c1 = sC[e1r];
            int s0 = ssrc[e0r], d0 = sdst[e0r];
            int s1 = ssrc[e1r], d1 = sdst[e1r];
#pragma unroll
            for (int j = 0; j < 8; j++) {
                int f = 64 * nw + 8 * j + 2 * t;
                float bb0 = sb2[f], bb1 = sb2[f + 1];
                if (ge0 < E) {
                    float2 h = *(const float2*)(g_h + s0 * NF + f);
                    red2(g_agg + d0 * NF + f,
                         (C[j][0] + bb0) * c0 * h.x,
                         (C[j][1] + bb1) * c0 * h.y);
                }
                if (ge1 < E) {
                    float2 h = *(const float2*)(g_h + s1 * NF + f);
                    red2(g_agg + d1 * NF + f,
                         (C[j][2] + bb0) * c1 * h.x,
                         (C[j][3] + bb1) * c1 * h.y);
                }
            }
        }
    }
}

// ===========================================================================
// lin1 on mma.sync: h = x @ lin1_w^T (no bias); also zeroes g_agg slice.
// smem: WH 0, WL 32768, XH 65536, XL 98304  (131072 bytes)
// ===========================================================================
#define LIN1_SMEM 131072

__global__ __launch_bounds__(512, 1)
void lin1_kernel(const float* __restrict__ x, const float* __restrict__ w, int N) {
    extern __shared__ char smem[];
    uint32_t sbase = smem_u32(smem);
    int tid = threadIdx.x;
    int wp = tid >> 5, lane = tid & 31;
    int mw = wp & 7, nw = wp >> 3;
    int g = lane >> 2, t = lane & 3;

    int nb = blockIdx.x * TN;

    // zero this block's slice of g_agg (replaces zero_agg kernel)
    {
        int zrows = NN - nb; if (zrows > TN) zrows = TN;
        if (zrows > 0) {
            float4* az = (float4*)(g_agg + nb * NF);
            int n4 = zrows * (NF / 4);
            for (int i = tid; i < n4; i += 512)
                az[i] = make_float4(0.f, 0.f, 0.f, 0.f);
        }
    }

    for (int idx = tid; idx < NF * HID; idx += 512) {
        int f = idx >> 7, k = idx & 127;
        __nv_bfloat16 h, lo; split_bf16(w[idx], h, lo);
        int o = phy(f, k, 256);
        *(__nv_bfloat16*)(smem + 0 + o) = h;
        *(__nv_bfloat16*)(smem + 32768 + o) = lo;
    }
    for (int idx = tid; idx < TN * HID; idx += 512) {
        int n = idx >> 7, k = idx & 127;
        float v = (nb + n < N) ? x[(nb + n) * HID + k] : 0.f;
        __nv_bfloat16 h, lo; split_bf16(v, h, lo);
        int o = phy(n, k, 256);
        *(__nv_bfloat16*)(smem + 65536 + o) = h;
        *(__nv_bfloat16*)(smem + 98304 + o) = lo;
    }
    __syncthreads();

    float C[8][4];
#pragma unroll
    for (int j = 0; j < 8; j++)
#pragma unroll
        for (int q = 0; q < 4; q++) C[j][q] = 0.f;
    warp_mma<8, 256, 256>(sbase + 65536, sbase + 98304,
                          sbase + 0, sbase + 32768,
                          16 * mw, 64 * nw, lane, C);

    int r0 = nb + 16 * mw + g, r1 = r0 + 8;
#pragma unroll
    for (int j = 0; j < 8; j++) {
        int f = 64 * nw + 8 * j + 2 * t;
        if (r0 < N) *(float2*)(g_h + r0 * NF + f) = make_float2(C[j][0], C[j][1]);
        if (r1 < N) *(float2*)(g_h + r1 * NF + f) = make_float2(C[j][2], C[j][3]);
    }
}

// ===========================================================================
// out on mma.sync: out = ssp(agg @ lin2^T + b2) @ lin_w^T + bo.
// smem: W2H 0, W2L 32768, WOH 65536, WOL 98304, AH 131072, AL 163840,
//       sb2 196608, sbo 197120   (197632 bytes)
// ===========================================================================
#define OUT_SMEM 197632

__global__ __launch_bounds__(512, 1)
void out_kernel(const float* __restrict__ w2, const float* __restrict__ b2,
                const float* __restrict__ wo, const float* __restrict__ bo,
                float* __restrict__ out, int N)
{
    extern __shared__ char smem[];
    uint32_t sbase = smem_u32(smem);
    int tid = threadIdx.x;
    int wp = tid >> 5, lane = tid & 31;
    int mw = wp & 7, nw = wp >> 3;
    int g = lane >> 2, t = lane & 3;

    float* sb2 = (float*)(smem + 196608);
    float* sbo = (float*)(smem + 197120);

    for (int idx = tid; idx < NF * NF; idx += 512) {
        int f = idx >> 7, k = idx & 127;
        int o = phy(f, k, 256);
        __nv_bfloat16 h, lo;
        split_bf16(w2[idx], h, lo);
        *(__nv_bfloat16*)(smem + 0 + o) = h;
        *(__nv_bfloat16*)(smem + 32768 + o) = lo;
        split_bf16(wo[idx], h, lo);
        *(__nv_bfloat16*)(smem + 65536 + o) = h;
        *(__nv_bfloat16*)(smem + 98304 + o) = lo;
    }
    if (tid < NF) { sb2[tid] = b2[tid]; sbo[tid] = bo[tid]; }

    int nb = blockIdx.x * TN;
    for (int idx = tid; idx < TN * NF; idx += 512) {
        int n = idx >> 7, k = idx & 127;
        float v = (nb + n < N) ? g_agg[(nb + n) * NF + k] : 0.f;
        __nv_bfloat16 h, lo; split_bf16(v, h, lo);
        int o = phy(n, k, 256);
        *(__nv_bfloat16*)(smem + 131072 + o) = h;
        *(__nv_bfloat16*)(smem + 163840 + o) = lo;
    }
    __syncthreads();

    // GEMM1: C = agg @ lin2^T
    float C[8][4];
#pragma unroll
    for (int j = 0; j < 8; j++)
#pragma unroll
        for (int q = 0; q < 4; q++) C[j][q] = 0.f;
    warp_mma<8, 256, 256>(sbase + 131072, sbase + 163840,
                          sbase + 0, sbase + 32768,
                          16 * mw, 64 * nw, lane, C);
    __syncthreads();   // all A reads done before overwrite

    // epilogue: bias + ssp -> split -> back into A buffers (as h2)
    int e0r = 16 * mw + g, e1r = e0r + 8;
#pragma unroll
    for (int j = 0; j < 8; j++) {
        int f = 64 * nw + 8 * j + 2 * t;
        float bb0 = sb2[f], bb1 = sb2[f + 1];
        float v00 = sspf(C[j][0] + bb0), v01 = sspf(C[j][1] + bb1);
        float v10 = sspf(C[j][2] + bb0), v11 = sspf(C[j][3] + bb1);
        __nv_bfloat16 h0, l0, h1, l1;
        __nv_bfloat162 hh, ll;
        split_bf16(v00, h0, l0); split_bf16(v01, h1, l1);
        hh.x = h0; hh.y = h1; ll.x = l0; ll.y = l1;
        int o0 = phy(e0r, f, 256);
        *(__nv_bfloat162*)(smem + 131072 + o0) = hh;
        *(__nv_bfloat162*)(smem + 163840 + o0) = ll;
        split_bf16(v10, h0, l0); split_bf16(v11, h1, l1);
        hh.x = h0; hh.y = h1; ll.x = l0; ll.y = l1;
        int o1 = phy(e1r, f, 256);
        *(__nv_bfloat162*)(smem + 131072 + o1) = hh;
        *(__nv_bfloat162*)(smem + 163840 + o1) = ll;
    }
    __syncthreads();

    // GEMM2: C = h2 @ lin_w^T
#pragma unroll
    for (int j = 0; j < 8; j++)
#pragma unroll
        for (int q = 0; q < 4; q++) C[j][q] = 0.f;
    warp_mma<8, 256, 256>(sbase + 131072, sbase + 163840,
                          sbase + 65536, sbase + 98304,
                          16 * mw, 64 * nw, lane, C);

    int r0 = nb + e0r, r1 = nb + e1r;
#pragma unroll
    for (int j = 0; j < 8; j++) {
        int f = 64 * nw + 8 * j + 2 * t;
        float bb0 = sbo[f], bb1 = sbo[f + 1];
        if (r0 < N)
            *(float2*)(out + r0 * HID + f) = make_float2(C[j][0] + bb0, C[j][1] + bb1);
        if (r1 < N)
            *(float2*)(out + r1 * HID + f) = make_float2(C[j][2] + bb0, C[j][3] + bb1);
    }
}

// ---------------------------------------------------------------------------

extern "C" void kernel_launch(void* const* d_in, const int* in_sizes, int n_in,
                              void* d_out, int out_size) {
    const float* x      = (const float*)d_in[0];
    const int*   eidx   = (const int*)  d_in[1];
    const float* ew     = (const float*)d_in[2];
    const float* ea     = (const float*)d_in[3];
    const float* mlp_w1 = (const float*)d_in[4];
    const float* mlp_b1 = (const float*)d_in[5];
    const float* mlp_w2 = (const float*)d_in[6];
    const float* mlp_b2 = (const float*)d_in[7];
    const float* lin1_w = (const float*)d_in[8];
    const float* lin2_w = (const float*)d_in[9];
    const float* lin2_b = (const float*)d_in[10];
    const float* lin_w  = (const float*)d_in[11];
    const float* lin_b  = (const float*)d_in[12];
    float* out = (float*)d_out;

    int N = in_sizes[0] / HID;
    int E = in_sizes[2];

    cudaFuncSetAttribute(edge_kernel, cudaFuncAttributeMaxDynamicSharedMemorySize, EDGE_SMEM);
    cudaFuncSetAttribute(lin1_kernel, cudaFuncAttributeMaxDynamicSharedMemorySize, LIN1_SMEM);
    cudaFuncSetAttribute(out_kernel,  cudaFuncAttributeMaxDynamicSharedMemorySize, OUT_SMEM);

    int ntile_n = (N + TN - 1) / TN;

    lin1_kernel<<<ntile_n, 512, LIN1_SMEM>>>(x, lin1_w, N);
    edge_kernel<<<152, 512, EDGE_SMEM>>>(ea, eidx, ew,
                                         mlp_w1, mlp_b1, mlp_w2, mlp_b2, E);
    out_kernel<<<ntile_n, 512, OUT_SMEM>>>(lin2_w, lin2_b, lin_w, lin_b, out, N);
}